// round 9
// baseline (speedup 1.0000x reference)
#include <cuda_runtime.h>
#include <cuda_bf16.h>
#include <math.h>
#include <stdint.h>

// Problem constants
#define XYDIM 16
#define ZDIM  16
#define SNUM  4096     // 16*16*16
#define VNUM  2048
#define BNUM  8
#define LNUM  32
#define WNUM  8

#define LOG5F 1.6094379124341003f

// ---------------- scratch (device globals: no allocation allowed) ----------------
__device__ float g_lse[SNUM];                      // row logsumexp of emis_w
__device__ float g_LQT[(size_t)VNUM * SNUM];       // smoothed log-emission, TRANSPOSED [v][s]  (32MB)
__device__ float g_allemis[LNUM * BNUM * SNUM];    // (L,B,S) emission sums + folded prior/amax
__device__ float g_P7[7 * SNUM];                   // exp(logp - amax), fixed-offset slots, [k][s]
__device__ float g_amax[SNUM];
__device__ float g_plse[1];                        // prior logsumexp

// ---------------- small PTX helpers ----------------
__device__ __forceinline__ unsigned smem_u32(const void* p) {
    unsigned a;
    asm("{ .reg .u64 t; cvta.to.shared.u64 t, %1; cvt.u32.u64 %0, t; }" : "=r"(a) : "l"(p));
    return a;
}
__device__ __forceinline__ unsigned my_cluster_rank() {
    unsigned r; asm("mov.u32 %0, %%cluster_ctarank;" : "=r"(r)); return r;
}
__device__ __forceinline__ unsigned mapa_rank(unsigned addr, unsigned rank) {
    unsigned r; asm("mapa.shared::cluster.u32 %0, %1, %2;" : "=r"(r) : "r"(addr), "r"(rank));
    return r;
}
__device__ __forceinline__ void st_cluster_2f(unsigned addr, float a, float b) {
    unsigned long long v;
    asm("mov.b64 %0, {%1, %2};" : "=l"(v) : "f"(a), "f"(b));
    asm volatile("st.shared::cluster.b64 [%0], %1;" :: "r"(addr), "l"(v) : "memory");
}
__device__ __forceinline__ void st_cluster_1f(unsigned addr, float a) {
    asm volatile("st.shared::cluster.b32 [%0], %1;" :: "r"(addr), "r"(__float_as_uint(a)) : "memory");
}
__device__ __forceinline__ void mbar_init(unsigned addr, unsigned count) {
    asm volatile("mbarrier.init.shared.b64 [%0], %1;" :: "r"(addr), "r"(count) : "memory");
}
__device__ __forceinline__ void mbar_arrive_local(unsigned addr) {
    asm volatile("mbarrier.arrive.shared.b64 _, [%0];" :: "r"(addr) : "memory");
}
__device__ __forceinline__ void mbar_arrive_remote(unsigned caddr) {
    asm volatile("mbarrier.arrive.release.cluster.shared::cluster.b64 _, [%0];"
                 :: "r"(caddr) : "memory");
}
__device__ __forceinline__ void mbar_wait_acq_cluster(unsigned addr, unsigned parity) {
    asm volatile(
        "{\n\t.reg .pred P;\n\t"
        "MBW_%=:\n\t"
        "mbarrier.try_wait.parity.acquire.cluster.shared::cta.b64 P, [%0], %1, 0x989680;\n\t"
        "@!P bra MBW_%=;\n\t}"
        :: "r"(addr), "r"(parity) : "memory");
}
__device__ __forceinline__ void cluster_sync_all() {
    asm volatile("barrier.cluster.arrive.aligned;" ::: "memory");
    asm volatile("barrier.cluster.wait.aligned;" ::: "memory");
}

// ---------------- K_prep: fused row-lse (4096 blocks) + trans (16) + prior (1) ----------------
__global__ void k_prep(const float* __restrict__ emis,
                       const float* __restrict__ tw,
                       const float* __restrict__ pw) {
    int bid = blockIdx.x;
    int t = threadIdx.x;                 // 256 threads

    if (bid < SNUM) {
        int s = bid;
        const float4* row = reinterpret_cast<const float4*>(emis + (size_t)s * VNUM);
        float4 a = row[t];
        float4 b = row[t + 256];
        float mx = fmaxf(fmaxf(fmaxf(a.x, a.y), fmaxf(a.z, a.w)),
                         fmaxf(fmaxf(b.x, b.y), fmaxf(b.z, b.w)));
        __shared__ float red[8];
        #pragma unroll
        for (int o = 16; o; o >>= 1) mx = fmaxf(mx, __shfl_xor_sync(0xffffffffu, mx, o));
        if ((t & 31) == 0) red[t >> 5] = mx;
        __syncthreads();
        mx = red[0];
        #pragma unroll
        for (int k = 1; k < 8; k++) mx = fmaxf(mx, red[k]);
        float se = __expf(a.x - mx) + __expf(a.y - mx) + __expf(a.z - mx) + __expf(a.w - mx)
                 + __expf(b.x - mx) + __expf(b.y - mx) + __expf(b.z - mx) + __expf(b.w - mx);
        #pragma unroll
        for (int o = 16; o; o >>= 1) se += __shfl_xor_sync(0xffffffffu, se, o);
        __syncthreads();
        if ((t & 31) == 0) red[t >> 5] = se;
        __syncthreads();
        if (t == 0) {
            float sum = 0.f;
            #pragma unroll
            for (int k = 0; k < 8; k++) sum += red[k];
            g_lse[s] = mx + __logf(sum);
        }
    } else if (bid < SNUM + 16) {
        // transition log-softmax with stable valid-first pairing
        int j = (bid - SNUM) * 256 + t;
        int x = j & 15, y = (j >> 4) & 15, z = j >> 8;
        bool val[7] = { true, x < 15, x > 0, y < 15, y > 0, z < 15, z < 14 };
        float wv[7];
        int r = 0;
        float M = -INFINITY;
        #pragma unroll
        for (int i = 0; i < 7; i++) {
            if (val[i]) { wv[i] = tw[j * 7 + r]; r++; M = fmaxf(M, wv[i]); }
            else wv[i] = 0.f;
        }
        float sum = 0.f;
        #pragma unroll
        for (int i = 0; i < 7; i++) if (val[i]) sum += __expf(wv[i] - M);
        g_amax[j] = -__logf(sum);
        #pragma unroll
        for (int i = 0; i < 7; i++)
            g_P7[i * SNUM + j] = val[i] ? __expf(wv[i] - M) : 0.f;
    } else {
        // prior logsumexp
        float v[16];
        float mx = -INFINITY;
        #pragma unroll
        for (int k = 0; k < 16; k++) { v[k] = pw[t + 256 * k]; mx = fmaxf(mx, v[k]); }
        __shared__ float red2[8];
        #pragma unroll
        for (int o = 16; o; o >>= 1) mx = fmaxf(mx, __shfl_xor_sync(0xffffffffu, mx, o));
        if ((t & 31) == 0) red2[t >> 5] = mx;
        __syncthreads();
        mx = red2[0];
        #pragma unroll
        for (int k = 1; k < 8; k++) mx = fmaxf(mx, red2[k]);
        float se = 0.f;
        #pragma unroll
        for (int k = 0; k < 16; k++) se += __expf(v[k] - mx);
        #pragma unroll
        for (int o = 16; o; o >>= 1) se += __shfl_xor_sync(0xffffffffu, se, o);
        __syncthreads();
        if ((t & 31) == 0) red2[t >> 5] = se;
        __syncthreads();
        if (t == 0) {
            float sum = 0.f;
            #pragma unroll
            for (int k = 0; k < 8; k++) sum += red2[k];
            g_plse[0] = mx + __logf(sum);
        }
    }
}

// ---------------- K2: 5-point (y,x) smoothing -> transposed log table ----------------
__global__ void k_smooth(const float* __restrict__ emis) {
    __shared__ float sm[256][33];
    int v0 = blockIdx.x * 32;
    int z  = blockIdx.y;
    int t = threadIdx.x;
    int w = t >> 5, l = t & 31;
    int sbase = z * 256;
    #pragma unroll 4
    for (int rr = 0; rr < 32; rr++) {
        int r = w * 32 + rr;
        int s = sbase + r;
        float x = emis[(size_t)s * VNUM + v0 + l];
        sm[r][l] = __expf(x - g_lse[s]);
    }
    __syncthreads();
    int p = t;
    int x = p & 15, y = p >> 4;
    int pu = (y < 15) ? p + 16 : p;
    int pd = (y > 0)  ? p - 16 : p;
    int pl = (x < 15) ? p + 1  : p;
    int pr = (x > 0)  ? p - 1  : p;
    #pragma unroll 4
    for (int i = 0; i < 32; i++) {
        float Q = sm[p][i] + sm[pu][i] + sm[pd][i] + sm[pl][i] + sm[pr][i];
        g_LQT[(size_t)(v0 + i) * SNUM + sbase + p] = __logf(Q) - LOG5F;
    }
}

// ---------------- K3: token gather-sum -> all_emis, folding prior (l=0) / amax (l>0) ----------------
__global__ void k_gather(const int* __restrict__ stories, const float* __restrict__ pw) {
    int b = blockIdx.x, l = blockIdx.y;
    __shared__ int tok[WNUM];
    if (threadIdx.x < WNUM) tok[threadIdx.x] = stories[(b * LNUM + l) * WNUM + threadIdx.x];
    __syncthreads();
    int t = threadIdx.x;
    float plse = g_plse[0];
    float4* dst = reinterpret_cast<float4*>(g_allemis + ((size_t)l * BNUM + b) * SNUM);
    float4 acc[4];
    #pragma unroll
    for (int i = 0; i < 4; i++) {
        int j = (t + 256 * i) * 4;
        if (l == 0) {
            float4 q = *reinterpret_cast<const float4*>(&pw[j]);
            acc[i] = make_float4(q.x - plse, q.y - plse, q.z - plse, q.w - plse);
        } else {
            acc[i] = *reinterpret_cast<const float4*>(&g_amax[j]);
        }
    }
    #pragma unroll
    for (int w2 = 0; w2 < WNUM; w2++) {
        int tk = tok[w2];
        if (tk < VNUM) {
            const float4* row = reinterpret_cast<const float4*>(g_LQT + (size_t)tk * SNUM);
            #pragma unroll
            for (int i = 0; i < 4; i++) {
                float4 r = row[t + 256 * i];
                acc[i].x += r.x; acc[i].y += r.y; acc[i].z += r.z; acc[i].w += r.w;
            }
        }
    }
    #pragma unroll
    for (int i = 0; i < 4; i++) dst[t + 256 * i] = acc[i];
}

// ---------------- K5: forward recursion — cluster(2) z-split, 2048 states/CTA ----------------
// rank0 owns z 0..7 (global 0..2047), rank1 owns z 8..15 (2048..4095).
// Stencil offsets {0,+1,-1,+16,-16,+256,+512}: all z-coupling (+256,+512) flows
// rank1 -> rank0 only. rank1 ships SCORE halo (v) + its local max each step; both
// CTAs use m = max(mloc, mpeer) == exact global max (reference-identical
// underflow/-inf pattern). rank0's crossing warps exponentiate the halo with the
// same m. One mbarrier wait (count=2: local + peer thread0) + 2 __syncthreads/step.
__global__ void __launch_bounds__(1024, 1) __cluster_dims__(2, 1, 1)
k_forward(float* __restrict__ out) {
    __shared__ float sp[16 + 2048 + 1024];  // [front16 zeros | local 2048 | halo buf0/buf1 (zeros on rank1)]
    __shared__ float red[32];
    __shared__ float mloc[2];               // reduced local max, per buffer (thread0)
    __shared__ float mpeer[2];              // reduced peer max (remote write)
    __shared__ __align__(8) unsigned long long mb_full[2];

    int b = blockIdx.x >> 1;
    unsigned rank = my_cluster_rank();
    int t = threadIdx.x;                    // 1024 threads, 2 contiguous states each
    int wid = t >> 5, lane = t & 31;
    int lj = t * 2;
    int jg = (int)(rank * 2048) + lj;

    unsigned fullb[2] = { smem_u32(&mb_full[0]), smem_u32(&mb_full[1]) };
    unsigned mpeer_b  = smem_u32(&mpeer[0]);
    unsigned spb      = smem_u32(sp);

    if (t == 0) { mbar_init(fullb[0], 2); mbar_init(fullb[1], 2); }
    if (t < 16) sp[t] = 0.f;
    sp[16 + 2048 + t] = 0.f;                // zero both halo buffers
    __syncthreads();
    cluster_sync_all();                      // peer mbarriers + zeros ready

    unsigned peer = rank ^ 1;
    unsigned r_full[2]  = { mapa_rank(fullb[0], peer), mapa_rank(fullb[1], peer) };
    unsigned r_mpeer[2] = { mapa_rank(mpeer_b, peer), mapa_rank(mpeer_b + 4, peer) };
    unsigned r_halo0 = 0;                   // rank1 t<256: slot in rank0's halo buf0
    if (t < 256) r_halo0 = mapa_rank(spb + (16 + 2048 + lj) * 4, 0);
    unsigned r_halo1 = r_halo0 + 512 * 4;

    // persistent transition rows (float2, [k][s] layout)
    float p7r[7][2];
    #pragma unroll
    for (int k = 0; k < 7; k++) {
        float2 a = *reinterpret_cast<const float2*>(&g_P7[k * SNUM + jg]);
        p7r[k][0] = a.x; p7r[k][1] = a.y;
    }

    // l = 0: score0 fully materialized by k_gather (em + prior - plse)
    float v0, v1;
    {
        float2 e = *reinterpret_cast<const float2*>(&g_allemis[(size_t)b * SNUM + jg]);
        v0 = e.x; v1 = e.y;
        *reinterpret_cast<float2*>(&out[(size_t)b * SNUM + jg]) = e;
    }
    {
        float lm = fmaxf(v0, v1);
        #pragma unroll
        for (int o = 16; o; o >>= 1) lm = fmaxf(lm, __shfl_xor_sync(0xffffffffu, lm, o));
        if (lane == 0) red[wid] = lm;
        if (rank == 1 && t < 256) st_cluster_2f(r_halo1, v0, v1);   // v-halo for step 1 (buf 1)
        __syncthreads();
        if (t == 0) {
            const float4* rp = reinterpret_cast<const float4*>(red);
            float4 a0 = rp[0], a1 = rp[1], a2 = rp[2], a3 = rp[3];
            float4 a4 = rp[4], a5 = rp[5], a6 = rp[6], a7 = rp[7];
            float q0 = fmaxf(fmaxf(a0.x, a0.y), fmaxf(a0.z, a0.w));
            float q1 = fmaxf(fmaxf(a1.x, a1.y), fmaxf(a1.z, a1.w));
            float q2 = fmaxf(fmaxf(a2.x, a2.y), fmaxf(a2.z, a2.w));
            float q3 = fmaxf(fmaxf(a3.x, a3.y), fmaxf(a3.z, a3.w));
            float q4 = fmaxf(fmaxf(a4.x, a4.y), fmaxf(a4.z, a4.w));
            float q5 = fmaxf(fmaxf(a5.x, a5.y), fmaxf(a5.z, a5.w));
            float q6 = fmaxf(fmaxf(a6.x, a6.y), fmaxf(a6.z, a6.w));
            float q7 = fmaxf(fmaxf(a7.x, a7.y), fmaxf(a7.z, a7.w));
            float mlv = fmaxf(fmaxf(fmaxf(q0, q1), fmaxf(q2, q3)),
                              fmaxf(fmaxf(q4, q5), fmaxf(q6, q7)));
            mloc[1] = mlv;
            st_cluster_1f(r_mpeer[1], mlv);
            mbar_arrive_remote(r_full[1]);
            mbar_arrive_local(fullb[1]);
        }
    }

    for (int l = 1; l < LNUM; l++) {
        int bb = l & 1;
        unsigned par = (unsigned)(((l - 1) >> 1) & 1);
        // head: wait both maxima (local + peer), exact global max
        mbar_wait_acq_cluster(fullb[bb], par);
        float m = fmaxf(mloc[bb], mpeer[bb]);

        // phase A: sp = exp(v - m); prefetch emissions; ±1 shfl
        float s0 = __expf(v0 - m), s1 = __expf(v1 - m);
        *reinterpret_cast<float2*>(&sp[16 + lj]) = make_float2(s0, s1);
        float2 em = *reinterpret_cast<const float2*>(
            g_allemis + ((size_t)l * BNUM + b) * SNUM + jg);
        float rgt = __shfl_down_sync(0xffffffffu, s0, 1);  // +1 across thread edge
        float lft = __shfl_up_sync(0xffffffffu, s1, 1);    // -1 across thread edge
        __syncthreads();

        // phase B
        int hOff = bb << 9;
        float2 a16 = *reinterpret_cast<const float2*>(&sp[16 + lj + 16]);
        float2 d16 = *reinterpret_cast<const float2*>(&sp[16 + lj - 16]);
        int i256 = lj + 256, i512 = lj + 512;
        bool c256 = (i256 >= 2048), c512 = (i512 >= 2048);
        float2 q256 = *reinterpret_cast<const float2*>(&sp[16 + i256 + (c256 ? hOff : 0)]);
        float2 q512 = *reinterpret_cast<const float2*>(&sp[16 + i512 + (c512 ? hOff : 0)]);
        // crossing reads are raw scores (or zeros on rank1, P7-masked): exponentiate
        // with the same global m; fminf clamp keeps the rank1 dummy path finite.
        float n256x = c256 ? __expf(fminf(q256.x - m, 0.f)) : q256.x;
        float n256y = c256 ? __expf(fminf(q256.y - m, 0.f)) : q256.y;
        float n512x = c512 ? __expf(fminf(q512.x - m, 0.f)) : q512.x;
        float n512y = c512 ? __expf(fminf(q512.y - m, 0.f)) : q512.y;

        float acc0 = p7r[0][0] * s0 + p7r[1][0] * s1 + p7r[2][0] * lft
                   + p7r[3][0] * a16.x + p7r[4][0] * d16.x
                   + p7r[5][0] * n256x + p7r[6][0] * n512x;
        float acc1 = p7r[0][1] * s1 + p7r[1][1] * rgt + p7r[2][1] * s0
                   + p7r[3][1] * a16.y + p7r[4][1] * d16.y
                   + p7r[5][1] * n256y + p7r[6][1] * n512y;
        v0 = em.x + __logf(acc0) + m;     // amax folded into em
        v1 = em.y + __logf(acc1) + m;
        *reinterpret_cast<float2*>(out + ((size_t)l * BNUM + b) * SNUM + jg)
            = make_float2(v0, v1);

        float lm = fmaxf(v0, v1);
        #pragma unroll
        for (int o = 16; o; o >>= 1) lm = fmaxf(lm, __shfl_xor_sync(0xffffffffu, lm, o));
        if (lane == 0) red[wid] = lm;
        if (l < LNUM - 1) {
            if (rank == 1 && t < 256)      // v-halo for step l+1 into buffer (l+1)&1
                st_cluster_2f(((l + 1) & 1) ? r_halo1 : r_halo0, v0, v1);
        }
        __syncthreads();
        if (t == 0 && l < LNUM - 1) {
            const float4* rp = reinterpret_cast<const float4*>(red);
            float4 a0 = rp[0], a1 = rp[1], a2 = rp[2], a3 = rp[3];
            float4 a4 = rp[4], a5 = rp[5], a6 = rp[6], a7 = rp[7];
            float q0 = fmaxf(fmaxf(a0.x, a0.y), fmaxf(a0.z, a0.w));
            float q1 = fmaxf(fmaxf(a1.x, a1.y), fmaxf(a1.z, a1.w));
            float q2 = fmaxf(fmaxf(a2.x, a2.y), fmaxf(a2.z, a2.w));
            float q3 = fmaxf(fmaxf(a3.x, a3.y), fmaxf(a3.z, a3.w));
            float q4 = fmaxf(fmaxf(a4.x, a4.y), fmaxf(a4.z, a4.w));
            float q5 = fmaxf(fmaxf(a5.x, a5.y), fmaxf(a5.z, a5.w));
            float q6 = fmaxf(fmaxf(a6.x, a6.y), fmaxf(a6.z, a6.w));
            float q7 = fmaxf(fmaxf(a7.x, a7.y), fmaxf(a7.z, a7.w));
            float mlv = fmaxf(fmaxf(fmaxf(q0, q1), fmaxf(q2, q3)),
                              fmaxf(fmaxf(q4, q5), fmaxf(q6, q7)));
            int nb = (l + 1) & 1;
            mloc[nb] = mlv;
            st_cluster_1f(r_mpeer[nb], mlv);
            mbar_arrive_remote(r_full[nb]);
            mbar_arrive_local(fullb[nb]);
        }
    }
    cluster_sync_all();   // keep peer smem alive for any in-flight remote ops
}

// ---------------- launch ----------------
extern "C" void kernel_launch(void* const* d_in, const int* in_sizes, int n_in,
                              void* d_out, int out_size) {
    const int*   stories = nullptr;
    const float* trans_w = nullptr;
    const float* emis_w  = nullptr;
    const float* prior_w = nullptr;
    for (int i = 0; i < n_in; i++) {
        switch (in_sizes[i]) {
            case BNUM * LNUM * WNUM: stories = (const int*)d_in[i];   break; // 2048
            case SNUM * 7:           trans_w = (const float*)d_in[i]; break; // 28672
            case SNUM * VNUM:        emis_w  = (const float*)d_in[i]; break; // 8388608
            case SNUM:               prior_w = (const float*)d_in[i]; break; // 4096
            default: break; // story_length scalar
        }
    }
    float* out = (float*)d_out;

    k_prep<<<SNUM + 16 + 1, 256>>>(emis_w, trans_w, prior_w);
    k_smooth<<<dim3(VNUM / 32, ZDIM), 256>>>(emis_w);
    k_gather<<<dim3(BNUM, LNUM), 256>>>(stories, prior_w);
    k_forward<<<2 * BNUM, 1024>>>(out);
}

// round 13
// speedup vs baseline: 1.2628x; 1.2628x over previous
#include <cuda_runtime.h>
#include <cuda_bf16.h>
#include <math.h>
#include <stdint.h>

// Problem constants
#define XYDIM 16
#define ZDIM  16
#define SNUM  4096     // 16*16*16
#define VNUM  2048
#define BNUM  8
#define LNUM  32
#define WNUM  8

#define LOG5F 1.6094379124341003f

// ---------------- scratch (device globals: no allocation allowed) ----------------
__device__ float g_lse[SNUM];                      // row logsumexp of emis_w
__device__ float g_LQT[(size_t)VNUM * SNUM];       // smoothed log-emission, TRANSPOSED [v][s]  (32MB)
__device__ float g_allemis[LNUM * BNUM * SNUM];    // (L,B,S) emission sums + folded prior/amax
__device__ float g_P7[7 * SNUM];                   // exp(logp - amax), fixed-offset slots, [k][s]
__device__ float g_amax[SNUM];
__device__ float g_plse[1];                        // prior logsumexp

// warp-wide fp32 max via integer redux (sm_103a has no redux.f32).
// Order-preserving map fp32 -> s32: i>=0 ? i : i^0x7fffffff (handles ±inf).
__device__ __forceinline__ float redux_max_f32(float v) {
    int i = __float_as_int(v);
    i = (i >= 0) ? i : (i ^ 0x7fffffff);
    int r;
    asm volatile("redux.sync.max.s32 %0, %1, 0xffffffff;" : "=r"(r) : "r"(i));
    r = (r >= 0) ? r : (r ^ 0x7fffffff);
    return __int_as_float(r);
}

// ---------------- K_prep: fused row-lse (4096 blocks) + trans (16) + prior (1) ----------------
__global__ void k_prep(const float* __restrict__ emis,
                       const float* __restrict__ tw,
                       const float* __restrict__ pw) {
    int bid = blockIdx.x;
    int t = threadIdx.x;                 // 256 threads

    if (bid < SNUM) {
        int s = bid;
        const float4* row = reinterpret_cast<const float4*>(emis + (size_t)s * VNUM);
        float4 a = row[t];
        float4 b = row[t + 256];
        float mx = fmaxf(fmaxf(fmaxf(a.x, a.y), fmaxf(a.z, a.w)),
                         fmaxf(fmaxf(b.x, b.y), fmaxf(b.z, b.w)));
        __shared__ float red[8];
        #pragma unroll
        for (int o = 16; o; o >>= 1) mx = fmaxf(mx, __shfl_xor_sync(0xffffffffu, mx, o));
        if ((t & 31) == 0) red[t >> 5] = mx;
        __syncthreads();
        mx = red[0];
        #pragma unroll
        for (int k = 1; k < 8; k++) mx = fmaxf(mx, red[k]);
        float se = __expf(a.x - mx) + __expf(a.y - mx) + __expf(a.z - mx) + __expf(a.w - mx)
                 + __expf(b.x - mx) + __expf(b.y - mx) + __expf(b.z - mx) + __expf(b.w - mx);
        #pragma unroll
        for (int o = 16; o; o >>= 1) se += __shfl_xor_sync(0xffffffffu, se, o);
        __syncthreads();
        if ((t & 31) == 0) red[t >> 5] = se;
        __syncthreads();
        if (t == 0) {
            float sum = 0.f;
            #pragma unroll
            for (int k = 0; k < 8; k++) sum += red[k];
            g_lse[s] = mx + __logf(sum);
        }
    } else if (bid < SNUM + 16) {
        // transition log-softmax with stable valid-first pairing
        int j = (bid - SNUM) * 256 + t;
        int x = j & 15, y = (j >> 4) & 15, z = j >> 8;
        bool val[7] = { true, x < 15, x > 0, y < 15, y > 0, z < 15, z < 14 };
        float wv[7];
        int r = 0;
        float M = -INFINITY;
        #pragma unroll
        for (int i = 0; i < 7; i++) {
            if (val[i]) { wv[i] = tw[j * 7 + r]; r++; M = fmaxf(M, wv[i]); }
            else wv[i] = 0.f;
        }
        float sum = 0.f;
        #pragma unroll
        for (int i = 0; i < 7; i++) if (val[i]) sum += __expf(wv[i] - M);
        g_amax[j] = -__logf(sum);
        #pragma unroll
        for (int i = 0; i < 7; i++)
            g_P7[i * SNUM + j] = val[i] ? __expf(wv[i] - M) : 0.f;
    } else {
        // prior logsumexp
        float v[16];
        float mx = -INFINITY;
        #pragma unroll
        for (int k = 0; k < 16; k++) { v[k] = pw[t + 256 * k]; mx = fmaxf(mx, v[k]); }
        __shared__ float red2[8];
        #pragma unroll
        for (int o = 16; o; o >>= 1) mx = fmaxf(mx, __shfl_xor_sync(0xffffffffu, mx, o));
        if ((t & 31) == 0) red2[t >> 5] = mx;
        __syncthreads();
        mx = red2[0];
        #pragma unroll
        for (int k = 1; k < 8; k++) mx = fmaxf(mx, red2[k]);
        float se = 0.f;
        #pragma unroll
        for (int k = 0; k < 16; k++) se += __expf(v[k] - mx);
        #pragma unroll
        for (int o = 16; o; o >>= 1) se += __shfl_xor_sync(0xffffffffu, se, o);
        __syncthreads();
        if ((t & 31) == 0) red2[t >> 5] = se;
        __syncthreads();
        if (t == 0) {
            float sum = 0.f;
            #pragma unroll
            for (int k = 0; k < 8; k++) sum += red2[k];
            g_plse[0] = mx + __logf(sum);
        }
    }
}

// ---------------- K2: 5-point (y,x) smoothing -> transposed log table ----------------
__global__ void k_smooth(const float* __restrict__ emis) {
    __shared__ float sm[256][33];
    int v0 = blockIdx.x * 32;
    int z  = blockIdx.y;
    int t = threadIdx.x;
    int w = t >> 5, l = t & 31;
    int sbase = z * 256;
    #pragma unroll 4
    for (int rr = 0; rr < 32; rr++) {
        int r = w * 32 + rr;
        int s = sbase + r;
        float x = emis[(size_t)s * VNUM + v0 + l];
        sm[r][l] = __expf(x - g_lse[s]);
    }
    __syncthreads();
    int p = t;
    int x = p & 15, y = p >> 4;
    int pu = (y < 15) ? p + 16 : p;
    int pd = (y > 0)  ? p - 16 : p;
    int pl = (x < 15) ? p + 1  : p;
    int pr = (x > 0)  ? p - 1  : p;
    #pragma unroll 4
    for (int i = 0; i < 32; i++) {
        float Q = sm[p][i] + sm[pu][i] + sm[pd][i] + sm[pl][i] + sm[pr][i];
        g_LQT[(size_t)(v0 + i) * SNUM + sbase + p] = __logf(Q) - LOG5F;
    }
}

// ---------------- K3: token gather-sum -> all_emis, folding prior (l=0) / amax (l>0) ----------------
__global__ void k_gather(const int* __restrict__ stories, const float* __restrict__ pw) {
    int b = blockIdx.x, l = blockIdx.y;
    __shared__ int tok[WNUM];
    if (threadIdx.x < WNUM) tok[threadIdx.x] = stories[(b * LNUM + l) * WNUM + threadIdx.x];
    __syncthreads();
    int t = threadIdx.x;
    float plse = g_plse[0];
    float4* dst = reinterpret_cast<float4*>(g_allemis + ((size_t)l * BNUM + b) * SNUM);
    float4 acc[4];
    #pragma unroll
    for (int i = 0; i < 4; i++) {
        int j = (t + 256 * i) * 4;
        if (l == 0) {
            float4 q = *reinterpret_cast<const float4*>(&pw[j]);
            acc[i] = make_float4(q.x - plse, q.y - plse, q.z - plse, q.w - plse);
        } else {
            acc[i] = *reinterpret_cast<const float4*>(&g_amax[j]);
        }
    }
    #pragma unroll
    for (int w2 = 0; w2 < WNUM; w2++) {
        int tk = tok[w2];
        if (tk < VNUM) {
            const float4* row = reinterpret_cast<const float4*>(g_LQT + (size_t)tk * SNUM);
            #pragma unroll
            for (int i = 0; i < 4; i++) {
                float4 r = row[t + 256 * i];
                acc[i].x += r.x; acc[i].y += r.y; acc[i].z += r.z; acc[i].w += r.w;
            }
        }
    }
    #pragma unroll
    for (int i = 0; i < 4; i++) dst[t + 256 * i] = acc[i];
}

// ---------------- K5: forward recursion — 1024 threads, 4 contiguous states/thread ----------------
// Offsets {0,+1,-1,+16,-16,+256,+512}. ±1 = intra-thread + shfl-by-1 (thread-edge
// invalid cases sit on x faces, P7==0 masks clamp garbage). ±16/+256/+512 via
// LDS.128 from zero-padded [halo16 | 4096 | halo512] (faces masked by P7==0).
// Block max via redux.sync.max.s32 on order-preserving keys: tail publishes warp
// max to red[wid]; head does 1 LDS(red[lane]) + 1 redux -> exact block max.
// Emissions for step l+1 prefetched during step l's compute phase.
__global__ void __launch_bounds__(1024, 1)
k_forward(float* __restrict__ out) {
    __shared__ float sp[16 + SNUM + 512];   // [front16 | 4096 | back512]
    __shared__ float red[32];
    int b = blockIdx.x;
    int t = threadIdx.x;                 // 1024 threads, 4 contiguous states each
    int wid = t >> 5, lane = t & 31;
    int j0 = t * 4;

    // persistent transition rows (coalesced float4 loads, [k][s] layout)
    float p7r[7][4];
    #pragma unroll
    for (int k = 0; k < 7; k++) {
        float4 a = *reinterpret_cast<const float4*>(&g_P7[k * SNUM + j0]);
        p7r[k][0] = a.x; p7r[k][1] = a.y; p7r[k][2] = a.z; p7r[k][3] = a.w;
    }

    // zero halos once (never overwritten; P7==0 masks any read of them)
    if (t < 16)  sp[t] = 0.f;
    if (t < 512) sp[16 + SNUM + t] = 0.f;

    // l = 0: score0 already fully materialized by k_gather (em + prior - plse)
    float v[4];
    {
        float4 e = *reinterpret_cast<const float4*>(&g_allemis[(size_t)b * SNUM + j0]);
        v[0] = e.x; v[1] = e.y; v[2] = e.z; v[3] = e.w;
        *reinterpret_cast<float4*>(&out[(size_t)b * SNUM + j0]) = e;
    }
    {
        float lm = fmaxf(fmaxf(v[0], v[1]), fmaxf(v[2], v[3]));
        lm = redux_max_f32(lm);
        if (lane == 0) red[wid] = lm;
    }
    // prefetch emissions for l = 1
    float4 emv = *reinterpret_cast<const float4*>(
        g_allemis + ((size_t)1 * BNUM + b) * SNUM + j0);

    for (int l = 1; l < LNUM; l++) {
        __syncthreads();                 // red[] published; prev sp reads retired
        // head: block max = redux over the 32 warp maxima
        float m = redux_max_f32(red[lane]);

        // phase A: sp = exp(score - m); publish; ±1 shfl
        float s0 = __expf(v[0] - m), s1 = __expf(v[1] - m);
        float s2 = __expf(v[2] - m), s3 = __expf(v[3] - m);
        *reinterpret_cast<float4*>(&sp[16 + j0]) = make_float4(s0, s1, s2, s3);
        float rgt = __shfl_down_sync(0xffffffffu, s0, 1);  // +1 across thread edge
        float lft = __shfl_up_sync(0xffffffffu, s3, 1);    // -1 across thread edge
        __syncthreads();                 // sp ready

        // phase B: ±16, +256, +512 via LDS.128; compute
        float4 u16 = *reinterpret_cast<const float4*>(&sp[16 + j0 + 16]);
        float4 d16 = *reinterpret_cast<const float4*>(&sp[16 + j0 - 16]);
        float4 u256 = *reinterpret_cast<const float4*>(&sp[16 + j0 + 256]);
        float4 u512 = *reinterpret_cast<const float4*>(&sp[16 + j0 + 512]);
        float sarr[4] = { s0, s1, s2, s3 };
        float n16[4]  = { u16.x, u16.y, u16.z, u16.w };
        float m16[4]  = { d16.x, d16.y, d16.z, d16.w };
        float n256[4] = { u256.x, u256.y, u256.z, u256.w };
        float n512[4] = { u512.x, u512.y, u512.z, u512.w };
        float em[4] = { emv.x, emv.y, emv.z, emv.w };
        float lm = -INFINITY;
        #pragma unroll
        for (int st = 0; st < 4; st++) {
            float rn = (st < 3) ? sarr[st + 1] : rgt;
            float ln = (st > 0) ? sarr[st - 1] : lft;
            float acc = p7r[0][st] * sarr[st]
                      + p7r[1][st] * rn
                      + p7r[2][st] * ln
                      + p7r[3][st] * n16[st]
                      + p7r[4][st] * m16[st]
                      + p7r[5][st] * n256[st]
                      + p7r[6][st] * n512[st];
            v[st] = em[st] + __logf(acc) + m;   // amax folded into em
            lm = fmaxf(lm, v[st]);
        }
        *reinterpret_cast<float4*>(out + ((size_t)l * BNUM + b) * SNUM + j0)
            = make_float4(v[0], v[1], v[2], v[3]);
        // prefetch next step's emissions (clamped index; harmless re-read on last step)
        int ln2 = (l + 1 < LNUM) ? l + 1 : LNUM - 1;
        emv = *reinterpret_cast<const float4*>(
            g_allemis + ((size_t)ln2 * BNUM + b) * SNUM + j0);
        // tail: publish warp max
        lm = redux_max_f32(lm);
        if (lane == 0) red[wid] = lm;
    }
}

// ---------------- launch ----------------
extern "C" void kernel_launch(void* const* d_in, const int* in_sizes, int n_in,
                              void* d_out, int out_size) {
    const int*   stories = nullptr;
    const float* trans_w = nullptr;
    const float* emis_w  = nullptr;
    const float* prior_w = nullptr;
    for (int i = 0; i < n_in; i++) {
        switch (in_sizes[i]) {
            case BNUM * LNUM * WNUM: stories = (const int*)d_in[i];   break; // 2048
            case SNUM * 7:           trans_w = (const float*)d_in[i]; break; // 28672
            case SNUM * VNUM:        emis_w  = (const float*)d_in[i]; break; // 8388608
            case SNUM:               prior_w = (const float*)d_in[i]; break; // 4096
            default: break; // story_length scalar
        }
    }
    float* out = (float*)d_out;

    k_prep<<<SNUM + 16 + 1, 256>>>(emis_w, trans_w, prior_w);
    k_smooth<<<dim3(VNUM / 32, ZDIM), 256>>>(emis_w);
    k_gather<<<dim3(BNUM, LNUM), 256>>>(stories, prior_w);
    k_forward<<<BNUM, 1024>>>(out);
}